// round 1
// baseline (speedup 1.0000x reference)
#include <cuda_runtime.h>
#include <cuda_bf16.h>
#include <cstdint>

#define K_DIM 4096
#define N_DIM 4096
#define M_DIM 16384
#define NUM_VEC ((N_DIM * K_DIM) / 8)

// Scratch (allocation-free rule: __device__ globals)
__device__ __nv_bfloat16 g_w_hi[(size_t)N_DIM * K_DIM];
__device__ __nv_bfloat16 g_w_lo[(size_t)N_DIM * K_DIM];
__device__ __nv_bfloat16 g_x_hi[(size_t)M_DIM * K_DIM];
__device__ __nv_bfloat16 g_x_lo[(size_t)M_DIM * K_DIM];

// ---------------------------------------------------------------------------
// Kernel 1: VPTQ quantize weight -> q_weight, split into bf16 hi/lo
// one thread per 8-dim vector
// ---------------------------------------------------------------------------
__global__ void quantize_split_w(const float* __restrict__ weight,
                                 const float* __restrict__ centroids) {
    __shared__ float sc[2048];   // 256 centroids x 8
    __shared__ float scc[256];   // |c|^2
    const int tid = threadIdx.x;
    for (int i = tid; i < 2048; i += 256) sc[i] = centroids[i];
    __syncthreads();
    if (tid < 256) {
        float s = 0.f;
#pragma unroll
        for (int j = 0; j < 8; ++j) { float c = sc[tid * 8 + j]; s += c * c; }
        scc[tid] = s;
    }
    __syncthreads();

    const int v = blockIdx.x * 256 + tid;
    const float4* wv = reinterpret_cast<const float4*>(weight + (size_t)v * 8);
    float4 v0 = wv[0], v1 = wv[1];
    float vec[8] = {v0.x, v0.y, v0.z, v0.w, v1.x, v1.y, v1.z, v1.w};

    float vv = 0.f;
#pragma unroll
    for (int j = 0; j < 8; ++j) vv += vec[j] * vec[j];
    float norm = __fsqrt_rn(vv) + 1e-8f;

    float nrm[8];
    float nn = 0.f;
#pragma unroll
    for (int j = 0; j < 8; ++j) {
        nrm[j] = __fdiv_rn(vec[j], norm);
        nn += nrm[j] * nrm[j];
    }

    int best = 0;
    float bestd = 3.402823e38f;
#pragma unroll 4
    for (int k = 0; k < 256; ++k) {
        const float4* c4 = reinterpret_cast<const float4*>(sc + k * 8);
        float4 c0 = c4[0], c1 = c4[1];
        float dot = nrm[0] * c0.x + nrm[1] * c0.y + nrm[2] * c0.z + nrm[3] * c0.w
                  + nrm[4] * c1.x + nrm[5] * c1.y + nrm[6] * c1.z + nrm[7] * c1.w;
        float d2 = nn - 2.0f * dot + scc[k];
        if (d2 < bestd) { bestd = d2; best = k; }  // strict '<' == argmin first-occurrence
    }

    const float* cb = sc + best * 8;
    float cd = 0.f;
#pragma unroll
    for (int j = 0; j < 8; ++j) cd += vec[j] * cb[j];
    float scale = __fdiv_rn(cd, scc[best] + 1e-8f);

    union { __nv_bfloat16 h[8]; uint4 u; } ph, pl;
#pragma unroll
    for (int j = 0; j < 8; ++j) {
        float q = cb[j] * scale;
        __nv_bfloat16 hi = __float2bfloat16(q);
        ph.h[j] = hi;
        pl.h[j] = __float2bfloat16(q - __bfloat162float(hi));  // exact residual in fp32
    }
    reinterpret_cast<uint4*>(g_w_hi)[v] = ph.u;
    reinterpret_cast<uint4*>(g_w_lo)[v] = pl.u;
}

// ---------------------------------------------------------------------------
// Kernel 2: split x into bf16 hi/lo  (one float4 per thread)
// ---------------------------------------------------------------------------
__global__ void split_x_kernel(const float* __restrict__ x) {
    const size_t gid = (size_t)blockIdx.x * 256 + threadIdx.x;
    float4 v = reinterpret_cast<const float4*>(x)[gid];
    float f[4] = {v.x, v.y, v.z, v.w};
    union { __nv_bfloat16 h[4]; uint2 u; } ph, pl;
#pragma unroll
    for (int j = 0; j < 4; ++j) {
        __nv_bfloat16 hi = __float2bfloat16(f[j]);
        ph.h[j] = hi;
        pl.h[j] = __float2bfloat16(f[j] - __bfloat162float(hi));
    }
    reinterpret_cast<uint2*>(g_x_hi)[gid] = ph.u;
    reinterpret_cast<uint2*>(g_x_lo)[gid] = pl.u;
}

// ---------------------------------------------------------------------------
// Kernel 3: GEMM  Y[M,N] = Xsplit @ Wsplit^T + bias   (bf16x3, fp32 accum)
// Tiles: 128x128x32, 256 threads, 8 warps in 2(M) x 4(N), warp tile 64x32.
// Smem rows padded to 40 bf16 (80B) -> conflict-free 32-bit fragment loads.
// ---------------------------------------------------------------------------
#define BM 128
#define BN 128
#define BK 32
#define PAD 40
#define NKT (K_DIM / BK)
#define SA_STAGE_ELEMS (2 * BM * PAD)  // hi+lo for one stage = 10240

__device__ __forceinline__ void cp16(uint32_t saddr, const void* g) {
    asm volatile("cp.async.cg.shared.global [%0], [%1], 16;\n" ::"r"(saddr), "l"(g));
}

__device__ __forceinline__ void mma16816(float* c, const uint32_t* a, const uint32_t* b) {
    asm volatile(
        "mma.sync.aligned.m16n8k16.row.col.f32.bf16.bf16.f32 "
        "{%0,%1,%2,%3}, {%4,%5,%6,%7}, {%8,%9}, {%0,%1,%2,%3};\n"
        : "+f"(c[0]), "+f"(c[1]), "+f"(c[2]), "+f"(c[3])
        : "r"(a[0]), "r"(a[1]), "r"(a[2]), "r"(a[3]), "r"(b[0]), "r"(b[1]));
}

__global__ __launch_bounds__(256, 1) void gemm_bf16x3(const float* __restrict__ bias,
                                                      float* __restrict__ Y) {
    extern __shared__ __nv_bfloat16 sm[];
    __nv_bfloat16* sA = sm;                        // [stage][var][128][PAD]
    __nv_bfloat16* sB = sm + 2 * SA_STAGE_ELEMS;   // same layout

    const int tid = threadIdx.x;
    const int wid = tid >> 5, lane = tid & 31;
    const int wm = wid >> 2, wn = wid & 3;         // 2 x 4 warp grid
    const int g = lane >> 2, t = lane & 3;
    const int m0 = blockIdx.y * BM, n0 = blockIdx.x * BN;

    float acc[4][4][4];
#pragma unroll
    for (int i = 0; i < 4; ++i)
#pragma unroll
        for (int j = 0; j < 4; ++j)
#pragma unroll
            for (int r = 0; r < 4; ++r) acc[i][j][r] = 0.f;

    // loader lambda: 128x32 tile = 512 16B chunks, 2 per thread per (matrix,var)
    auto load_stage = [&](int stage, int kt) {
        const int k0 = kt * BK;
#pragma unroll
        for (int i = 0; i < 2; ++i) {
            const int idx = tid + i * 256;
            const int row = idx >> 2;
            const int cu = idx & 3;
            const size_t gA = (size_t)(m0 + row) * K_DIM + k0 + cu * 8;
            const size_t gB = (size_t)(n0 + row) * K_DIM + k0 + cu * 8;
            const int sOffBase = row * PAD + cu * 8;
            // A hi / lo
            cp16((uint32_t)__cvta_generic_to_shared(
                     &sA[(stage * 2 + 0) * BM * PAD + sOffBase]), g_x_hi + gA);
            cp16((uint32_t)__cvta_generic_to_shared(
                     &sA[(stage * 2 + 1) * BM * PAD + sOffBase]), g_x_lo + gA);
            // B hi / lo
            cp16((uint32_t)__cvta_generic_to_shared(
                     &sB[(stage * 2 + 0) * BN * PAD + sOffBase]), g_w_hi + gB);
            cp16((uint32_t)__cvta_generic_to_shared(
                     &sB[(stage * 2 + 1) * BN * PAD + sOffBase]), g_w_lo + gB);
        }
    };

    load_stage(0, 0);
    asm volatile("cp.async.commit_group;\n");
    asm volatile("cp.async.wait_group 0;\n");
    __syncthreads();

    for (int kt = 0; kt < NKT; ++kt) {
        const int st = kt & 1;
        if (kt + 1 < NKT) {
            load_stage(st ^ 1, kt + 1);
            asm volatile("cp.async.commit_group;\n");
        }

        // ---- compute on stage st ----
#pragma unroll
        for (int ks = 0; ks < 2; ++ks) {
            uint32_t ah[4][4], al[4][4], bh[4][2], bl[4][2];
            const int kc = ks * 16 + t * 2;
#pragma unroll
            for (int i = 0; i < 4; ++i) {
                const int r = wm * 64 + i * 16 + g;
                const int bh0 = (st * 2 + 0) * BM * PAD + r * PAD;
                const int bl0 = (st * 2 + 1) * BM * PAD + r * PAD;
                ah[i][0] = *reinterpret_cast<const uint32_t*>(&sA[bh0 + kc]);
                ah[i][1] = *reinterpret_cast<const uint32_t*>(&sA[bh0 + 8 * PAD + kc]);
                ah[i][2] = *reinterpret_cast<const uint32_t*>(&sA[bh0 + kc + 8]);
                ah[i][3] = *reinterpret_cast<const uint32_t*>(&sA[bh0 + 8 * PAD + kc + 8]);
                al[i][0] = *reinterpret_cast<const uint32_t*>(&sA[bl0 + kc]);
                al[i][1] = *reinterpret_cast<const uint32_t*>(&sA[bl0 + 8 * PAD + kc]);
                al[i][2] = *reinterpret_cast<const uint32_t*>(&sA[bl0 + kc + 8]);
                al[i][3] = *reinterpret_cast<const uint32_t*>(&sA[bl0 + 8 * PAD + kc + 8]);
            }
#pragma unroll
            for (int j = 0; j < 4; ++j) {
                const int nr = wn * 32 + j * 8 + g;
                const int bbh = (st * 2 + 0) * BN * PAD + nr * PAD;
                const int bbl = (st * 2 + 1) * BN * PAD + nr * PAD;
                bh[j][0] = *reinterpret_cast<const uint32_t*>(&sB[bbh + kc]);
                bh[j][1] = *reinterpret_cast<const uint32_t*>(&sB[bbh + kc + 8]);
                bl[j][0] = *reinterpret_cast<const uint32_t*>(&sB[bbl + kc]);
                bl[j][1] = *reinterpret_cast<const uint32_t*>(&sB[bbl + kc + 8]);
            }
#pragma unroll
            for (int i = 0; i < 4; ++i)
#pragma unroll
                for (int j = 0; j < 4; ++j) {
                    mma16816(acc[i][j], ah[i], bh[j]);  // hi*hi
                    mma16816(acc[i][j], ah[i], bl[j]);  // hi*lo
                    mma16816(acc[i][j], al[i], bh[j]);  // lo*hi
                }
        }

        if (kt + 1 < NKT) asm volatile("cp.async.wait_group 0;\n");
        __syncthreads();
    }

    // ---- epilogue: += bias, write fp32 ----
#pragma unroll
    for (int i = 0; i < 4; ++i) {
#pragma unroll
        for (int j = 0; j < 4; ++j) {
            const int row = m0 + wm * 64 + i * 16 + g;
            const int col = n0 + wn * 32 + j * 8 + t * 2;
            const float b0 = __ldg(&bias[col]);
            const float b1 = __ldg(&bias[col + 1]);
            float2 r0 = make_float2(acc[i][j][0] + b0, acc[i][j][1] + b1);
            float2 r1 = make_float2(acc[i][j][2] + b0, acc[i][j][3] + b1);
            *reinterpret_cast<float2*>(&Y[(size_t)row * N_DIM + col]) = r0;
            *reinterpret_cast<float2*>(&Y[(size_t)(row + 8) * N_DIM + col]) = r1;
        }
    }
}

// ---------------------------------------------------------------------------
extern "C" void kernel_launch(void* const* d_in, const int* in_sizes, int n_in,
                              void* d_out, int out_size) {
    const float* x = (const float*)d_in[0];          // [4,4096,4096]
    const float* weight = (const float*)d_in[1];     // [4096,4096]
    const float* bias = (const float*)d_in[2];       // [4096]
    const float* centroids = (const float*)d_in[3];  // [256,8]
    float* Y = (float*)d_out;

    quantize_split_w<<<NUM_VEC / 256, 256>>>(weight, centroids);
    split_x_kernel<<<(M_DIM * (size_t)K_DIM / 4) / 256, 256>>>(x);

    cudaFuncSetAttribute(gemm_bf16x3, cudaFuncAttributeMaxDynamicSharedMemorySize,
                         4 * SA_STAGE_ELEMS * (int)sizeof(__nv_bfloat16));
    dim3 grid(N_DIM / BN, M_DIM / BM);
    gemm_bf16x3<<<grid, 256, 4 * SA_STAGE_ELEMS * sizeof(__nv_bfloat16)>>>(bias, Y);
}

// round 3
// speedup vs baseline: 1.1786x; 1.1786x over previous
#include <cuda_runtime.h>
#include <cuda_bf16.h>
#include <cstdint>

#define K_DIM 4096
#define N_DIM 4096
#define M_DIM 16384
#define NUM_VEC ((N_DIM * K_DIM) / 8)

__device__ __nv_bfloat16 g_w_hi[(size_t)N_DIM * K_DIM];
__device__ __nv_bfloat16 g_w_lo[(size_t)N_DIM * K_DIM];
__device__ __nv_bfloat16 g_x_hi[(size_t)M_DIM * K_DIM];
__device__ __nv_bfloat16 g_x_lo[(size_t)M_DIM * K_DIM];

// ===========================================================================
// Kernel 1: VPTQ quantize weight -> q_weight, split into bf16 hi/lo
// ===========================================================================
__global__ void quantize_split_w(const float* __restrict__ weight,
                                 const float* __restrict__ centroids) {
    __shared__ float sc[2048];
    __shared__ float scc[256];
    const int tid = threadIdx.x;
    for (int i = tid; i < 2048; i += 256) sc[i] = centroids[i];
    __syncthreads();
    if (tid < 256) {
        float s = 0.f;
#pragma unroll
        for (int j = 0; j < 8; ++j) { float c = sc[tid * 8 + j]; s += c * c; }
        scc[tid] = s;
    }
    __syncthreads();

    const int v = blockIdx.x * 256 + tid;
    const float4* wv = reinterpret_cast<const float4*>(weight + (size_t)v * 8);
    float4 v0 = wv[0], v1 = wv[1];
    float vec[8] = {v0.x, v0.y, v0.z, v0.w, v1.x, v1.y, v1.z, v1.w};

    float vv = 0.f;
#pragma unroll
    for (int j = 0; j < 8; ++j) vv += vec[j] * vec[j];
    float norm = __fsqrt_rn(vv) + 1e-8f;

    float nrm[8]; float nn = 0.f;
#pragma unroll
    for (int j = 0; j < 8; ++j) { nrm[j] = __fdiv_rn(vec[j], norm); nn += nrm[j] * nrm[j]; }

    int best = 0; float bestd = 3.402823e38f;
#pragma unroll 4
    for (int k = 0; k < 256; ++k) {
        const float4* c4 = reinterpret_cast<const float4*>(sc + k * 8);
        float4 c0 = c4[0], c1 = c4[1];
        float dot = nrm[0] * c0.x + nrm[1] * c0.y + nrm[2] * c0.z + nrm[3] * c0.w
                  + nrm[4] * c1.x + nrm[5] * c1.y + nrm[6] * c1.z + nrm[7] * c1.w;
        float d2 = nn - 2.0f * dot + scc[k];
        if (d2 < bestd) { bestd = d2; best = k; }
    }

    const float* cb = sc + best * 8;
    float cd = 0.f;
#pragma unroll
    for (int j = 0; j < 8; ++j) cd += vec[j] * cb[j];
    float scale = __fdiv_rn(cd, scc[best] + 1e-8f);

    union { __nv_bfloat16 h[8]; uint4 u; } ph, pl;
#pragma unroll
    for (int j = 0; j < 8; ++j) {
        float q = cb[j] * scale;
        __nv_bfloat16 hi = __float2bfloat16(q);
        ph.h[j] = hi;
        pl.h[j] = __float2bfloat16(q - __bfloat162float(hi));
    }
    reinterpret_cast<uint4*>(g_w_hi)[v] = ph.u;
    reinterpret_cast<uint4*>(g_w_lo)[v] = pl.u;
}

// ===========================================================================
// Kernel 2: split x into bf16 hi/lo
// ===========================================================================
__global__ void split_x_kernel(const float* __restrict__ x) {
    const size_t gid = (size_t)blockIdx.x * 256 + threadIdx.x;
    float4 v = reinterpret_cast<const float4*>(x)[gid];
    float f[4] = {v.x, v.y, v.z, v.w};
    union { __nv_bfloat16 h[4]; uint2 u; } ph, pl;
#pragma unroll
    for (int j = 0; j < 4; ++j) {
        __nv_bfloat16 hi = __float2bfloat16(f[j]);
        ph.h[j] = hi;
        pl.h[j] = __float2bfloat16(f[j] - __bfloat162float(hi));
    }
    reinterpret_cast<uint2*>(g_x_hi)[gid] = ph.u;
    reinterpret_cast<uint2*>(g_x_lo)[gid] = pl.u;
}

// ===========================================================================
// Kernel 3: GEMM  Y[M,N] = Xhi*Whi + Xhi*Wlo + Xlo*Whi + bias (fp32 accum)
// 128x128x64 tiles, 256 thr (8 warps 2x4, warp tile 64x32), ldmatrix frags,
// double-buffered cp.async. Stride 72 elems -> conflict-free LDSM.
// ===========================================================================
#define BM 128
#define BN 128
#define BK 64
#define SKP 72                       // row stride in elems (144 B)
#define NKT (K_DIM / BK)             // 64
#define AVAR (BM * SKP)              // elems per (var) buffer = 9216
// smem layout (elems): A: [stage2][var2][AVAR]  then B: same  => 8*AVAR total
#define SMEM_ELEMS (8 * AVAR)

__device__ __forceinline__ void cp16(uint32_t saddr, const void* g) {
    asm volatile("cp.async.cg.shared.global [%0], [%1], 16;\n" ::"r"(saddr), "l"(g));
}
__device__ __forceinline__ void ldsm4(uint32_t* r, uint32_t addr) {
    asm volatile("ldmatrix.sync.aligned.m8n8.x4.shared.b16 {%0,%1,%2,%3}, [%4];"
                 : "=r"(r[0]), "=r"(r[1]), "=r"(r[2]), "=r"(r[3]) : "r"(addr));
}
__device__ __forceinline__ void mma16816(float* c, const uint32_t* a, const uint32_t* b) {
    asm volatile(
        "mma.sync.aligned.m16n8k16.row.col.f32.bf16.bf16.f32 "
        "{%0,%1,%2,%3}, {%4,%5,%6,%7}, {%8,%9}, {%0,%1,%2,%3};\n"
        : "+f"(c[0]), "+f"(c[1]), "+f"(c[2]), "+f"(c[3])
        : "r"(a[0]), "r"(a[1]), "r"(a[2]), "r"(a[3]), "r"(b[0]), "r"(b[1]));
}

__global__ __launch_bounds__(256, 1) void gemm_bf16x3(const float* __restrict__ bias,
                                                      float* __restrict__ Y) {
    extern __shared__ __nv_bfloat16 sm[];
    const uint32_t smA = (uint32_t)__cvta_generic_to_shared(sm);
    const uint32_t smB = smA + 4u * AVAR * 2u;

    const int tid = threadIdx.x;
    const int wid = tid >> 5, lane = tid & 31;
    const int wm = wid >> 2, wn = wid & 3;   // 2 x 4 warp grid
    const int m0 = blockIdx.y * BM, n0 = blockIdx.x * BN;

    float acc[4][4][4];
#pragma unroll
    for (int i = 0; i < 4; ++i)
#pragma unroll
        for (int j = 0; j < 4; ++j)
#pragma unroll
            for (int r = 0; r < 4; ++r) acc[i][j][r] = 0.f;

    // ldmatrix per-lane offsets (elems)
    const int t8 = lane >> 3;                       // tile index 0..3
    const int rr = lane & 7;                        // row within tile
    // A: t&1 -> +8 rows, t>>1 -> +8 cols
    const int a_row = (t8 & 1) * 8 + rr;
    const int a_col = (t8 >> 1) * 8;
    // B: t>>1 -> +8 n-rows, t&1 -> +8 k-cols
    const int b_row = (t8 >> 1) * 8 + rr;
    const int b_col = (t8 & 1) * 8;

    // cp.async: 1024 chunks per buffer, 4 per thread
    auto load_stage = [&](int stage, int kt) {
        const int k0 = kt * BK;
        const uint32_t sAh = smA + (uint32_t)(stage * 2 + 0) * AVAR * 2u;
        const uint32_t sAl = smA + (uint32_t)(stage * 2 + 1) * AVAR * 2u;
        const uint32_t sBh = smB + (uint32_t)(stage * 2 + 0) * AVAR * 2u;
        const uint32_t sBl = smB + (uint32_t)(stage * 2 + 1) * AVAR * 2u;
#pragma unroll
        for (int j = 0; j < 4; ++j) {
            const int idx = tid + j * 256;
            const int row = idx >> 3;
            const int c = idx & 7;
            const size_t gA = (size_t)(m0 + row) * K_DIM + k0 + c * 8;
            const size_t gB = (size_t)(n0 + row) * K_DIM + k0 + c * 8;
            const uint32_t so = (uint32_t)(row * SKP + c * 8) * 2u;
            cp16(sAh + so, g_x_hi + gA);
            cp16(sAl + so, g_x_lo + gA);
            cp16(sBh + so, g_w_hi + gB);
            cp16(sBl + so, g_w_lo + gB);
        }
    };

    load_stage(0, 0);
    asm volatile("cp.async.commit_group;\n");

    for (int kt = 0; kt < NKT; ++kt) {
        const int st = kt & 1;
        if (kt + 1 < NKT) {
            load_stage(st ^ 1, kt + 1);
            asm volatile("cp.async.commit_group;\n");
            asm volatile("cp.async.wait_group 1;\n");
        } else {
            asm volatile("cp.async.wait_group 0;\n");
        }
        __syncthreads();

        const uint32_t sAh = smA + (uint32_t)(st * 2 + 0) * AVAR * 2u;
        const uint32_t sAl = smA + (uint32_t)(st * 2 + 1) * AVAR * 2u;
        const uint32_t sBh = smB + (uint32_t)(st * 2 + 0) * AVAR * 2u;
        const uint32_t sBl = smB + (uint32_t)(st * 2 + 1) * AVAR * 2u;

#pragma unroll
        for (int ks = 0; ks < 4; ++ks) {
            const int kc = ks * 16;
            uint32_t ah[4][4], al[4][4], bh[4][2], bl[4][2];
#pragma unroll
            for (int i = 0; i < 4; ++i) {
                const int r0 = wm * 64 + i * 16;
                const uint32_t off = (uint32_t)((r0 + a_row) * SKP + kc + a_col) * 2u;
                ldsm4(ah[i], sAh + off);
                ldsm4(al[i], sAl + off);
            }
#pragma unroll
            for (int p = 0; p < 2; ++p) {
                const int nb = wn * 32 + p * 16;
                const uint32_t off = (uint32_t)((nb + b_row) * SKP + kc + b_col) * 2u;
                uint32_t th[4], tl[4];
                ldsm4(th, sBh + off);
                ldsm4(tl, sBl + off);
                bh[2 * p][0] = th[0]; bh[2 * p][1] = th[1];
                bh[2 * p + 1][0] = th[2]; bh[2 * p + 1][1] = th[3];
                bl[2 * p][0] = tl[0]; bl[2 * p][1] = tl[1];
                bl[2 * p + 1][0] = tl[2]; bl[2 * p + 1][1] = tl[3];
            }
#pragma unroll
            for (int i = 0; i < 4; ++i)
#pragma unroll
                for (int j = 0; j < 4; ++j) {
                    mma16816(acc[i][j], ah[i], bh[j]);  // hi*hi
                    mma16816(acc[i][j], ah[i], bl[j]);  // hi*lo
                    mma16816(acc[i][j], al[i], bh[j]);  // lo*hi
                }
        }
        __syncthreads();
    }

    // ---- epilogue ----
    const int g = lane >> 2, t = lane & 3;
#pragma unroll
    for (int i = 0; i < 4; ++i) {
#pragma unroll
        for (int j = 0; j < 4; ++j) {
            const int row = m0 + wm * 64 + i * 16 + g;
            const int col = n0 + wn * 32 + j * 8 + t * 2;
            const float b0 = __ldg(&bias[col]);
            const float b1 = __ldg(&bias[col + 1]);
            float2 r0 = make_float2(acc[i][j][0] + b0, acc[i][j][1] + b1);
            float2 r1 = make_float2(acc[i][j][2] + b0, acc[i][j][3] + b1);
            *reinterpret_cast<float2*>(&Y[(size_t)row * N_DIM + col]) = r0;
            *reinterpret_cast<float2*>(&Y[(size_t)(row + 8) * N_DIM + col]) = r1;
        }
    }
}

// ===========================================================================
extern "C" void kernel_launch(void* const* d_in, const int* in_sizes, int n_in,
                              void* d_out, int out_size) {
    const float* x = (const float*)d_in[0];
    const float* weight = (const float*)d_in[1];
    const float* bias = (const float*)d_in[2];
    const float* centroids = (const float*)d_in[3];
    float* Y = (float*)d_out;

    quantize_split_w<<<NUM_VEC / 256, 256>>>(weight, centroids);
    split_x_kernel<<<(M_DIM * (size_t)K_DIM / 4) / 256, 256>>>(x);

    const int smem_bytes = SMEM_ELEMS * (int)sizeof(__nv_bfloat16);  // 147456
    cudaFuncSetAttribute(gemm_bf16x3, cudaFuncAttributeMaxDynamicSharedMemorySize, smem_bytes);
    dim3 grid(N_DIM / BN, M_DIM / BM);
    gemm_bf16x3<<<grid, 256, smem_bytes>>>(bias, Y);
}

// round 4
// speedup vs baseline: 1.2349x; 1.0478x over previous
#include <cuda_runtime.h>
#include <cuda_bf16.h>
#include <cstdint>

#define K_DIM 4096
#define N_DIM 4096
#define M_DIM 16384
#define NUM_VEC ((N_DIM * K_DIM) / 8)

__device__ __nv_bfloat16 g_w_hi[(size_t)N_DIM * K_DIM];
__device__ __nv_bfloat16 g_w_lo[(size_t)N_DIM * K_DIM];
__device__ __nv_bfloat16 g_x_hi[(size_t)M_DIM * K_DIM];
__device__ __nv_bfloat16 g_x_lo[(size_t)M_DIM * K_DIM];

// ===========================================================================
// Kernel 1: VPTQ quantize weight -> q_weight, split into bf16 hi/lo
// ===========================================================================
__global__ void quantize_split_w(const float* __restrict__ weight,
                                 const float* __restrict__ centroids) {
    __shared__ float sc[2048];
    __shared__ float scc[256];
    const int tid = threadIdx.x;
    for (int i = tid; i < 2048; i += 256) sc[i] = centroids[i];
    __syncthreads();
    if (tid < 256) {
        float s = 0.f;
#pragma unroll
        for (int j = 0; j < 8; ++j) { float c = sc[tid * 8 + j]; s += c * c; }
        scc[tid] = s;
    }
    __syncthreads();

    const int v = blockIdx.x * 256 + tid;
    const float4* wv = reinterpret_cast<const float4*>(weight + (size_t)v * 8);
    float4 v0 = wv[0], v1 = wv[1];
    float vec[8] = {v0.x, v0.y, v0.z, v0.w, v1.x, v1.y, v1.z, v1.w};

    float vv = 0.f;
#pragma unroll
    for (int j = 0; j < 8; ++j) vv += vec[j] * vec[j];
    float norm = __fsqrt_rn(vv) + 1e-8f;

    float nrm[8]; float nn = 0.f;
#pragma unroll
    for (int j = 0; j < 8; ++j) { nrm[j] = __fdiv_rn(vec[j], norm); nn += nrm[j] * nrm[j]; }

    int best = 0; float bestd = 3.402823e38f;
#pragma unroll 4
    for (int k = 0; k < 256; ++k) {
        const float4* c4 = reinterpret_cast<const float4*>(sc + k * 8);
        float4 c0 = c4[0], c1 = c4[1];
        float dot = nrm[0] * c0.x + nrm[1] * c0.y + nrm[2] * c0.z + nrm[3] * c0.w
                  + nrm[4] * c1.x + nrm[5] * c1.y + nrm[6] * c1.z + nrm[7] * c1.w;
        float d2 = nn - 2.0f * dot + scc[k];
        if (d2 < bestd) { bestd = d2; best = k; }
    }

    const float* cb = sc + best * 8;
    float cd = 0.f;
#pragma unroll
    for (int j = 0; j < 8; ++j) cd += vec[j] * cb[j];
    float scale = __fdiv_rn(cd, scc[best] + 1e-8f);

    union { __nv_bfloat16 h[8]; uint4 u; } ph, pl;
#pragma unroll
    for (int j = 0; j < 8; ++j) {
        float q = cb[j] * scale;
        __nv_bfloat16 hi = __float2bfloat16(q);
        ph.h[j] = hi;
        pl.h[j] = __float2bfloat16(q - __bfloat162float(hi));
    }
    reinterpret_cast<uint4*>(g_w_hi)[v] = ph.u;
    reinterpret_cast<uint4*>(g_w_lo)[v] = pl.u;
}

// ===========================================================================
// Kernel 2: split x into bf16 hi/lo
// ===========================================================================
__global__ void split_x_kernel(const float* __restrict__ x) {
    const size_t gid = (size_t)blockIdx.x * 256 + threadIdx.x;
    float4 v = reinterpret_cast<const float4*>(x)[gid];
    float f[4] = {v.x, v.y, v.z, v.w};
    union { __nv_bfloat16 h[4]; uint2 u; } ph, pl;
#pragma unroll
    for (int j = 0; j < 4; ++j) {
        __nv_bfloat16 hi = __float2bfloat16(f[j]);
        ph.h[j] = hi;
        pl.h[j] = __float2bfloat16(f[j] - __bfloat162float(hi));
    }
    reinterpret_cast<uint2*>(g_x_hi)[gid] = ph.u;
    reinterpret_cast<uint2*>(g_x_lo)[gid] = pl.u;
}

// ===========================================================================
// Kernel 3: GEMM  Y[M,N] = Xhi*Whi + Xhi*Wlo + Xlo*Whi + bias (fp32 accum)
// CTA tile 128x256x64, 256 thr (8 warps 2x4, warp tile 64x64), ldmatrix,
// double-buffered cp.async, ONE sync per kt.
// ===========================================================================
#define BM 128
#define BN 256
#define BK 64
#define SKP 72                        // row stride in elems (144 B), LDSM conflict-free
#define NKT (K_DIM / BK)              // 64
#define AV (BM * SKP)                 // 9216 elems  (A per var per stage)
#define BV (BN * SKP)                 // 18432 elems (B per var per stage)
#define SMEM_BYTES ((4 * AV + 4 * BV) * 2)  // 221184

__device__ __forceinline__ void cp16(uint32_t saddr, const void* g) {
    asm volatile("cp.async.cg.shared.global [%0], [%1], 16;\n" ::"r"(saddr), "l"(g));
}
__device__ __forceinline__ void ldsm4(uint32_t* r, uint32_t addr) {
    asm volatile("ldmatrix.sync.aligned.m8n8.x4.shared.b16 {%0,%1,%2,%3}, [%4];"
                 : "=r"(r[0]), "=r"(r[1]), "=r"(r[2]), "=r"(r[3]) : "r"(addr));
}
__device__ __forceinline__ void mma16816(float* c, const uint32_t* a, const uint32_t* b) {
    asm volatile(
        "mma.sync.aligned.m16n8k16.row.col.f32.bf16.bf16.f32 "
        "{%0,%1,%2,%3}, {%4,%5,%6,%7}, {%8,%9}, {%0,%1,%2,%3};\n"
        : "+f"(c[0]), "+f"(c[1]), "+f"(c[2]), "+f"(c[3])
        : "r"(a[0]), "r"(a[1]), "r"(a[2]), "r"(a[3]), "r"(b[0]), "r"(b[1]));
}

__global__ __launch_bounds__(256, 1) void gemm_bf16x3(const float* __restrict__ bias,
                                                      float* __restrict__ Y) {
    extern __shared__ __nv_bfloat16 sm[];
    const uint32_t smA = (uint32_t)__cvta_generic_to_shared(sm);
    const uint32_t smB = smA + 4u * AV * 2u;

    const int tid = threadIdx.x;
    const int wid = tid >> 5, lane = tid & 31;
    const int wm = wid >> 2, wn = wid & 3;   // 2 x 4 warp grid, warp tile 64x64
    const int m0 = blockIdx.y * BM, n0 = blockIdx.x * BN;

    float acc[4][8][4];
#pragma unroll
    for (int i = 0; i < 4; ++i)
#pragma unroll
        for (int j = 0; j < 8; ++j)
#pragma unroll
            for (int r = 0; r < 4; ++r) acc[i][j][r] = 0.f;

    // ldmatrix per-lane offsets
    const int t8 = lane >> 3, rr = lane & 7;
    const int a_row = (t8 & 1) * 8 + rr;
    const int a_col = (t8 >> 1) * 8;
    const int b_row = (t8 >> 1) * 8 + rr;
    const int b_col = (t8 & 1) * 8;

    auto load_stage = [&](int stage, int kt) {
        const int k0 = kt * BK;
        const uint32_t sAh = smA + (uint32_t)(stage * 2 + 0) * AV * 2u;
        const uint32_t sAl = smA + (uint32_t)(stage * 2 + 1) * AV * 2u;
        const uint32_t sBh = smB + (uint32_t)(stage * 2 + 0) * BV * 2u;
        const uint32_t sBl = smB + (uint32_t)(stage * 2 + 1) * BV * 2u;
        // A: 128 rows x 8 chunks = 1024, 4 per thread per var
#pragma unroll
        for (int j = 0; j < 4; ++j) {
            const int idx = tid + j * 256;
            const int row = idx >> 3, c = idx & 7;
            const size_t gA = (size_t)(m0 + row) * K_DIM + k0 + c * 8;
            const uint32_t so = (uint32_t)(row * SKP + c * 8) * 2u;
            cp16(sAh + so, g_x_hi + gA);
            cp16(sAl + so, g_x_lo + gA);
        }
        // B: 256 rows x 8 chunks = 2048, 8 per thread per var
#pragma unroll
        for (int j = 0; j < 8; ++j) {
            const int idx = tid + j * 256;
            const int row = idx >> 3, c = idx & 7;
            const size_t gB = (size_t)(n0 + row) * K_DIM + k0 + c * 8;
            const uint32_t so = (uint32_t)(row * SKP + c * 8) * 2u;
            cp16(sBh + so, g_w_hi + gB);
            cp16(sBl + so, g_w_lo + gB);
        }
    };

    load_stage(0, 0);
    asm volatile("cp.async.commit_group;\n");

    for (int kt = 0; kt < NKT; ++kt) {
        const int st = kt & 1;
        asm volatile("cp.async.wait_group 0;\n");
        __syncthreads();
        // After this sync every warp finished computing buffer st^1 last iter,
        // so prefetching kt+1 into st^1 is safe and overlaps compute of st.
        if (kt + 1 < NKT) {
            load_stage(st ^ 1, kt + 1);
            asm volatile("cp.async.commit_group;\n");
        }

        const uint32_t sAh = smA + (uint32_t)(st * 2 + 0) * AV * 2u;
        const uint32_t sAl = smA + (uint32_t)(st * 2 + 1) * AV * 2u;
        const uint32_t sBh = smB + (uint32_t)(st * 2 + 0) * BV * 2u;
        const uint32_t sBl = smB + (uint32_t)(st * 2 + 1) * BV * 2u;

#pragma unroll
        for (int ks = 0; ks < 4; ++ks) {
            const int kc = ks * 16;
            uint32_t ah[4][4], al[4][4];
#pragma unroll
            for (int i = 0; i < 4; ++i) {
                const uint32_t off =
                    (uint32_t)((wm * 64 + i * 16 + a_row) * SKP + kc + a_col) * 2u;
                ldsm4(ah[i], sAh + off);
                ldsm4(al[i], sAl + off);
            }
#pragma unroll
            for (int h = 0; h < 2; ++h) {       // 2 halves of 32 N-cols
                uint32_t bh[4][2], bl[4][2];
#pragma unroll
                for (int p = 0; p < 2; ++p) {
                    const int nb = wn * 64 + h * 32 + p * 16;
                    const uint32_t off =
                        (uint32_t)((nb + b_row) * SKP + kc + b_col) * 2u;
                    uint32_t th[4], tl[4];
                    ldsm4(th, sBh + off);
                    ldsm4(tl, sBl + off);
                    bh[2 * p][0] = th[0]; bh[2 * p][1] = th[1];
                    bh[2 * p + 1][0] = th[2]; bh[2 * p + 1][1] = th[3];
                    bl[2 * p][0] = tl[0]; bl[2 * p][1] = tl[1];
                    bl[2 * p + 1][0] = tl[2]; bl[2 * p + 1][1] = tl[3];
                }
#pragma unroll
                for (int i = 0; i < 4; ++i)
#pragma unroll
                    for (int jl = 0; jl < 4; ++jl) {
                        float* a4 = acc[i][h * 4 + jl];
                        mma16816(a4, ah[i], bh[jl]);  // hi*hi
                        mma16816(a4, ah[i], bl[jl]);  // hi*lo
                        mma16816(a4, al[i], bh[jl]);  // lo*hi
                    }
            }
        }
    }

    // ---- epilogue ----
    const int g = lane >> 2, t = lane & 3;
#pragma unroll
    for (int i = 0; i < 4; ++i) {
#pragma unroll
        for (int j = 0; j < 8; ++j) {
            const int row = m0 + wm * 64 + i * 16 + g;
            const int col = n0 + wn * 64 + j * 8 + t * 2;
            const float b0 = __ldg(&bias[col]);
            const float b1 = __ldg(&bias[col + 1]);
            float2 r0 = make_float2(acc[i][j][0] + b0, acc[i][j][1] + b1);
            float2 r1 = make_float2(acc[i][j][2] + b0, acc[i][j][3] + b1);
            *reinterpret_cast<float2*>(&Y[(size_t)row * N_DIM + col]) = r0;
            *reinterpret_cast<float2*>(&Y[(size_t)(row + 8) * N_DIM + col]) = r1;
        }
    }
}

// ===========================================================================
extern "C" void kernel_launch(void* const* d_in, const int* in_sizes, int n_in,
                              void* d_out, int out_size) {
    const float* x = (const float*)d_in[0];
    const float* weight = (const float*)d_in[1];
    const float* bias = (const float*)d_in[2];
    const float* centroids = (const float*)d_in[3];
    float* Y = (float*)d_out;

    quantize_split_w<<<NUM_VEC / 256, 256>>>(weight, centroids);
    split_x_kernel<<<(M_DIM * (size_t)K_DIM / 4) / 256, 256>>>(x);

    cudaFuncSetAttribute(gemm_bf16x3, cudaFuncAttributeMaxDynamicSharedMemorySize, SMEM_BYTES);
    dim3 grid(N_DIM / BN, M_DIM / BM);   // (16, 128)
    gemm_bf16x3<<<grid, 256, SMEM_BYTES>>>(bias, Y);
}